// round 2
// baseline (speedup 1.0000x reference)
#include <cuda_runtime.h>
#include <cstdint>

// DotReluAttention: out = relu(Q @ K^T / D) @ V
// B=2, H=8, S=4096, D=64, fp32 in/out.
// Fused two-GEMM kernel using mma.sync.m16n8k8 tf32.

#define BHEADS 16      // B*H
#define SEQ    4096
#define HD     64      // head dim
#define BM     128     // q rows per CTA
#define BN     64      // kv rows per iteration
#define NTHREADS 256   // 8 warps, each owns 16 q rows

// smem strides (in 32-bit words) chosen for conflict-free fragment access
#define SK 68   // K tile stride   (4*gid + tig distinct mod 32)
#define SV 72   // V tile stride   (8*tig + gid distinct mod 32)
#define SP 68   // P tile / Q staging stride

#define SMEM_WORDS (BM*SP + BN*SK + BN*SV)
#define SMEM_BYTES (SMEM_WORDS * 4)

__device__ __forceinline__ uint32_t f2tf32(float f) {
    uint32_t r;
    asm("cvt.rna.tf32.f32 %0, %1;" : "=r"(r) : "f"(f));
    return r;
}

__device__ __forceinline__ void mma_tf32(float* c, const uint32_t* a,
                                         uint32_t b0, uint32_t b1) {
    asm volatile(
        "mma.sync.aligned.m16n8k8.row.col.f32.tf32.tf32.f32 "
        "{%0,%1,%2,%3}, {%4,%5,%6,%7}, {%8,%9}, {%0,%1,%2,%3};\n"
        : "+f"(c[0]), "+f"(c[1]), "+f"(c[2]), "+f"(c[3])
        : "r"(a[0]), "r"(a[1]), "r"(a[2]), "r"(a[3]), "r"(b0), "r"(b1));
}

__global__ __launch_bounds__(NTHREADS)
void dot_relu_attn_kernel(const float* __restrict__ Q,
                          const float* __restrict__ K,
                          const float* __restrict__ V,
                          float* __restrict__ O) {
    extern __shared__ uint32_t smem[];
    uint32_t* sP = smem;                 // [BM][SP]  P tile (also Q staging)
    uint32_t* sK = sP + BM * SP;         // [BN][SK]
    uint32_t* sV = sK + BN * SK;         // [BN][SV]

    const int bh    = blockIdx.y;
    const int qbase = blockIdx.x * BM;

    const float* Qp = Q + ((size_t)bh * SEQ + qbase) * HD;
    const float* Kp = K + (size_t)bh * SEQ * HD;
    const float* Vp = V + (size_t)bh * SEQ * HD;
    float*       Op = O + ((size_t)bh * SEQ + qbase) * HD;

    const int tid  = threadIdx.x;
    const int warp = tid >> 5;
    const int lane = tid & 31;
    const int gid  = lane >> 2;   // groupID  (0..7)
    const int tig  = lane & 3;    // thread-in-group (0..3)
    const int m0   = warp * 16;   // this warp's q-row base within the tile

    // ---- Stage Q tile (BM x HD) into smem (tf32), then pull A fragments ----
    #pragma unroll
    for (int i = 0; i < 8; i++) {
        int idx = tid + i * NTHREADS;     // float4 index (2048 total)
        int row = idx >> 4;               // 16 float4 per row
        int c4  = idx & 15;
        float4 v = *reinterpret_cast<const float4*>(Qp + row * HD + c4 * 4);
        uint32_t* dst = &sP[row * SP + c4 * 4];
        dst[0] = f2tf32(v.x); dst[1] = f2tf32(v.y);
        dst[2] = f2tf32(v.z); dst[3] = f2tf32(v.w);
    }
    __syncthreads();

    uint32_t qa[8][4];   // Q A-fragments: 8 k-tiles over HD=64
    #pragma unroll
    for (int kt = 0; kt < 8; kt++) {
        int c = kt * 8 + tig;
        qa[kt][0] = sP[(m0 + gid)     * SP + c];
        qa[kt][1] = sP[(m0 + gid + 8) * SP + c];
        qa[kt][2] = sP[(m0 + gid)     * SP + c + 4];
        qa[kt][3] = sP[(m0 + gid + 8) * SP + c + 4];
    }
    __syncthreads();   // staging done; sP now free for P tiles

    float oacc[8][4];    // O accumulator: 16 x 64 per warp
    #pragma unroll
    for (int i = 0; i < 8; i++)
        #pragma unroll
        for (int j = 0; j < 4; j++) oacc[i][j] = 0.f;

    for (int kv = 0; kv < SEQ; kv += BN) {
        // ---- Load K,V tiles (BN x HD each) into smem, converting to tf32 ----
        #pragma unroll
        for (int i = 0; i < 4; i++) {
            int idx = tid + i * NTHREADS;   // float4 index (1024 total)
            int row = idx >> 4;
            int c4  = idx & 15;
            float4 kq = *reinterpret_cast<const float4*>(Kp + (kv + row) * HD + c4 * 4);
            uint32_t* dk = &sK[row * SK + c4 * 4];
            dk[0] = f2tf32(kq.x); dk[1] = f2tf32(kq.y);
            dk[2] = f2tf32(kq.z); dk[3] = f2tf32(kq.w);
            float4 vq = *reinterpret_cast<const float4*>(Vp + (kv + row) * HD + c4 * 4);
            uint32_t* dv = &sV[row * SV + c4 * 4];
            dv[0] = f2tf32(vq.x); dv[1] = f2tf32(vq.y);
            dv[2] = f2tf32(vq.z); dv[3] = f2tf32(vq.w);
        }
        __syncthreads();

        // ---- GEMM1: S = Q @ K^T   (per warp: 16 x BN, k over HD) ----
        float sacc[8][4];
        #pragma unroll
        for (int i = 0; i < 8; i++) {
            sacc[i][0] = 0.f; sacc[i][1] = 0.f; sacc[i][2] = 0.f; sacc[i][3] = 0.f;
        }
        #pragma unroll
        for (int kt = 0; kt < 8; kt++) {
            #pragma unroll
            for (int nt = 0; nt < 8; nt++) {
                // B[k][n] = K[n][k]; n = nt*8+gid, k = kt*8+tig (+4)
                uint32_t b0 = sK[(nt * 8 + gid) * SK + kt * 8 + tig];
                uint32_t b1 = sK[(nt * 8 + gid) * SK + kt * 8 + tig + 4];
                mma_tf32(sacc[nt], qa[kt], b0, b1);
            }
        }

        // ---- relu(S/64), write P tile (own rows only -> no barrier needed) ----
        #pragma unroll
        for (int nt = 0; nt < 8; nt++) {
            int col = nt * 8 + 2 * tig;
            sP[(m0 + gid)     * SP + col]     = f2tf32(fmaxf(sacc[nt][0] * (1.f/64.f), 0.f));
            sP[(m0 + gid)     * SP + col + 1] = f2tf32(fmaxf(sacc[nt][1] * (1.f/64.f), 0.f));
            sP[(m0 + gid + 8) * SP + col]     = f2tf32(fmaxf(sacc[nt][2] * (1.f/64.f), 0.f));
            sP[(m0 + gid + 8) * SP + col + 1] = f2tf32(fmaxf(sacc[nt][3] * (1.f/64.f), 0.f));
        }
        // same-warp smem write->read: program order suffices, no __syncthreads

        // ---- GEMM2: O += P @ V   (per warp: 16 x HD, k over BN) ----
        #pragma unroll
        for (int kt = 0; kt < 8; kt++) {
            uint32_t pa[4];
            int c = kt * 8 + tig;
            pa[0] = sP[(m0 + gid)     * SP + c];
            pa[1] = sP[(m0 + gid + 8) * SP + c];
            pa[2] = sP[(m0 + gid)     * SP + c + 4];
            pa[3] = sP[(m0 + gid + 8) * SP + c + 4];
            #pragma unroll
            for (int nt = 0; nt < 8; nt++) {
                // B[k][n] = V[k][n]; k = kt*8+tig (+4), n = nt*8+gid
                uint32_t b0 = sV[(kt * 8 + tig)     * SV + nt * 8 + gid];
                uint32_t b1 = sV[(kt * 8 + tig + 4) * SV + nt * 8 + gid];
                mma_tf32(oacc[nt], pa, b0, b1);
            }
        }
        __syncthreads();   // all reads of sK/sV done before next tile load
    }

    // ---- Epilogue: write O (each warp owns 16 full rows) ----
    #pragma unroll
    for (int nt = 0; nt < 8; nt++) {
        int col = nt * 8 + 2 * tig;
        float2 v0 = make_float2(oacc[nt][0], oacc[nt][1]);
        float2 v1 = make_float2(oacc[nt][2], oacc[nt][3]);
        *reinterpret_cast<float2*>(Op + (m0 + gid)     * HD + col) = v0;
        *reinterpret_cast<float2*>(Op + (m0 + gid + 8) * HD + col) = v1;
    }
}

extern "C" void kernel_launch(void* const* d_in, const int* in_sizes, int n_in,
                              void* d_out, int out_size) {
    const float* q = (const float*)d_in[0];
    const float* k = (const float*)d_in[1];
    const float* v = (const float*)d_in[2];
    float* o = (float*)d_out;

    // > 48KB static limit, so use dynamic smem (idempotent attribute set)
    cudaFuncSetAttribute(dot_relu_attn_kernel,
                         cudaFuncAttributeMaxDynamicSharedMemorySize, SMEM_BYTES);

    dim3 grid(SEQ / BM, BHEADS);
    dot_relu_attn_kernel<<<grid, NTHREADS, SMEM_BYTES>>>(q, k, v, o);
}

// round 5
// speedup vs baseline: 1.1723x; 1.1723x over previous
#include <cuda_runtime.h>
#include <cstdint>

// DotReluAttention: out = relu(Q @ K^T / 64) @ V ; B=2,H=8,S=4096,D=64 fp32.
// Legacy mma.sync tf32 path (tcgen05 unavailable under harness build flags).
// BM=256 (8 warps x 32 q-rows), BN=128. B fragments register-cached across the
// two 16-row A tiles; pair-permuted smem layouts give LDS.64 fragment loads.

#define SEQ 4096
#define HD  64
#define BM  256
#define BN  128
#define NTH 256
#define NITER  (SEQ/BN)
#define NCHUNK (BN/8)      // 16 kv-chunks per tile

// smem layout (32-bit words)
#define PSTR 72            // P/Q row stride  (72 mod 32 == 8 -> conflict-free LDS.64)
#define KSTR 72            // K row stride
#define VSTR 136           // V pair-row stride (136*? -> tig*136 mod 32 == tig*8)
#define KOFF (BM*PSTR)                    // 18432
#define VOFF (KOFF + BN*KSTR)             // 27648
#define SMEM_WORDS (VOFF + (BN/2)*VSTR)   // 36352
#define SMEM_BYTES (SMEM_WORDS*4)         // 145408

__device__ __forceinline__ uint32_t f2tf32(float f) {
    uint32_t r; asm("cvt.rna.tf32.f32 %0, %1;" : "=r"(r) : "f"(f)); return r;
}

__device__ __forceinline__ void mma8(float* c, const uint32_t* a,
                                     uint32_t b0, uint32_t b1) {
    asm volatile(
        "mma.sync.aligned.m16n8k8.row.col.f32.tf32.tf32.f32 "
        "{%0,%1,%2,%3}, {%4,%5,%6,%7}, {%8,%9}, {%0,%1,%2,%3};\n"
        : "+f"(c[0]), "+f"(c[1]), "+f"(c[2]), "+f"(c[3])
        : "r"(a[0]), "r"(a[1]), "r"(a[2]), "r"(a[3]), "r"(b0), "r"(b1));
}

__global__ __launch_bounds__(NTH, 1)
void dot_relu_attn_v3(const float* __restrict__ Q, const float* __restrict__ K,
                      const float* __restrict__ V, float* __restrict__ O) {
    extern __shared__ uint32_t sm[];
    uint32_t* sP = sm;           // [BM][PSTR]   P tile (Q staging first)
    uint32_t* sK = sm + KOFF;    // [BN][KSTR]   K tile, k pair-permuted
    uint32_t* sV = sm + VOFF;    // [BN/2][VSTR] V tile, kv pair-rows

    const int tid  = threadIdx.x;
    const int warp = tid >> 5;
    const int lane = tid & 31;
    const int gid  = lane >> 2;     // 0..7
    const int tig  = lane & 3;      // 0..3
    const int m0   = warp * 32;     // warp owns 32 q rows

    const int bh = blockIdx.y;
    const int qb = blockIdx.x * BM;
    const float* Qp = Q + ((size_t)bh * SEQ + qb) * HD;
    const float* Kp = K + (size_t)bh * SEQ * HD;
    const float* Vp = V + (size_t)bh * SEQ * HD;
    float*       Op = O + ((size_t)bh * SEQ + qb) * HD;

    // ---- Stage Q (BM x 64, tf32, pair-permuted k) ----
    #pragma unroll
    for (int i = 0; i < 16; i++) {
        int lin = tid + i * NTH;              // 4096 float4
        int row = lin >> 4, c4 = lin & 15;
        float4 v = *(const float4*)(Qp + row * HD + c4 * 4);
        uint32_t* d = &sP[row * PSTR + (c4 >> 1) * 8 + (c4 & 1)];
        d[0] = f2tf32(v.x); d[2] = f2tf32(v.y);
        d[4] = f2tf32(v.z); d[6] = f2tf32(v.w);
    }
    __syncthreads();

    // ---- A fragments for Q: qa[kt][mt] (LDS.64 pairs) ----
    uint32_t qa[8][2][4];
    #pragma unroll
    for (int kt = 0; kt < 8; kt++)
        #pragma unroll
        for (int mt = 0; mt < 2; mt++) {
            const uint32_t* p = &sP[(m0 + mt * 16 + gid) * PSTR + kt * 8 + 2 * tig];
            uint2 lo = *(const uint2*)p;
            uint2 hi = *(const uint2*)(p + 8 * PSTR);
            qa[kt][mt][0] = lo.x; qa[kt][mt][1] = hi.x;
            qa[kt][mt][2] = lo.y; qa[kt][mt][3] = hi.y;
        }
    __syncthreads();   // sP region now reused for P tiles

    float oacc[2][8][4];
    #pragma unroll
    for (int a = 0; a < 2; a++)
        #pragma unroll
        for (int b = 0; b < 8; b++)
            #pragma unroll
            for (int c = 0; c < 4; c++) oacc[a][b][c] = 0.f;

    // pair-permutation positions for the P write (cols 2tig, 2tig+1)
    const int pp0 = 2 * ((2 * tig)     & 3) + ((2 * tig)     >> 2);
    const int pp1 = 2 * ((2 * tig + 1) & 3) + ((2 * tig + 1) >> 2);

    #pragma unroll 1
    for (int it = 0; it < NITER; it++) {
        const float* Kt = Kp + (size_t)it * BN * HD;
        const float* Vt = Vp + (size_t)it * BN * HD;

        // ---- Load K,V tiles (each BN x 64), permuted layouts ----
        #pragma unroll
        for (int i = 0; i < 8; i++) {
            int lin = tid + i * NTH;          // 2048 float4 per tensor
            int row = lin >> 4, c4 = lin & 15;
            float4 kv = *(const float4*)(Kt + row * HD + c4 * 4);
            uint32_t* dk = &sK[row * KSTR + (c4 >> 1) * 8 + (c4 & 1)];
            dk[0] = f2tf32(kv.x); dk[2] = f2tf32(kv.y);
            dk[4] = f2tf32(kv.z); dk[6] = f2tf32(kv.w);
            float4 vv = *(const float4*)(Vt + row * HD + c4 * 4);
            uint32_t* dv = &sV[((row >> 3) * 4 + (row & 3)) * VSTR
                               + c4 * 8 + ((row >> 2) & 1)];
            dv[0] = f2tf32(vv.x); dv[2] = f2tf32(vv.y);
            dv[4] = f2tf32(vv.z); dv[6] = f2tf32(vv.w);
        }
        __syncthreads();

        // ---- Fused chunk loop: 8 kv columns at a time ----
        #pragma unroll 2
        for (int nk = 0; nk < NCHUNK; nk++) {
            // GEMM1 B fragments: cached once, reused for both m-tiles
            uint2 bc[8];
            const uint32_t* kb = &sK[(nk * 8 + gid) * KSTR + 2 * tig];
            #pragma unroll
            for (int kt = 0; kt < 8; kt++) bc[kt] = *(const uint2*)(kb + kt * 8);

            #pragma unroll
            for (int mt = 0; mt < 2; mt++) {
                float s[4] = {0.f, 0.f, 0.f, 0.f};
                #pragma unroll
                for (int kt = 0; kt < 8; kt++)
                    mma8(s, qa[kt][mt], bc[kt].x, bc[kt].y);
                // relu -> tf32 -> P (own rows; pair-permuted columns)
                uint32_t* pw = &sP[(m0 + mt * 16 + gid) * PSTR + nk * 8];
                pw[pp0]            = f2tf32(fmaxf(s[0], 0.f));
                pw[pp1]            = f2tf32(fmaxf(s[1], 0.f));
                pw[8 * PSTR + pp0] = f2tf32(fmaxf(s[2], 0.f));
                pw[8 * PSTR + pp1] = f2tf32(fmaxf(s[3], 0.f));
            }
            __syncwarp();

            // GEMM2 A fragments (P chunk), both m-tiles resident
            uint32_t pa[2][4];
            #pragma unroll
            for (int mt = 0; mt < 2; mt++) {
                const uint32_t* pr = &sP[(m0 + mt * 16 + gid) * PSTR + nk * 8 + 2 * tig];
                uint2 lo = *(const uint2*)pr;
                uint2 hi = *(const uint2*)(pr + 8 * PSTR);
                pa[mt][0] = lo.x; pa[mt][1] = hi.x;
                pa[mt][2] = lo.y; pa[mt][3] = hi.y;
            }
            // GEMM2: B fragment loaded once per (nk, n2), used by both m-tiles
            const uint32_t* vb = &sV[(nk * 4 + tig) * VSTR + gid * 2];
            #pragma unroll
            for (int n2 = 0; n2 < 8; n2++) {
                uint2 b = *(const uint2*)(vb + n2 * 16);
                mma8(oacc[0][n2], pa[0], b.x, b.y);
                mma8(oacc[1][n2], pa[1], b.x, b.y);
            }
        }
        __syncthreads();
    }

    // ---- Epilogue: O_out = O / 64 ----
    #pragma unroll
    for (int mt = 0; mt < 2; mt++) {
        float* r0 = Op + (size_t)(m0 + mt * 16 + gid) * HD;
        float* r1 = r0 + 8 * HD;
        #pragma unroll
        for (int n2 = 0; n2 < 8; n2++) {
            int col = n2 * 8 + 2 * tig;
            *(float2*)(r0 + col) = make_float2(oacc[mt][n2][0] * (1.f/64.f),
                                               oacc[mt][n2][1] * (1.f/64.f));
            *(float2*)(r1 + col) = make_float2(oacc[mt][n2][2] * (1.f/64.f),
                                               oacc[mt][n2][3] * (1.f/64.f));
        }
    }
}

extern "C" void kernel_launch(void* const* d_in, const int* in_sizes, int n_in,
                              void* d_out, int out_size) {
    const float* q = (const float*)d_in[0];
    const float* k = (const float*)d_in[1];
    const float* v = (const float*)d_in[2];
    float* o = (float*)d_out;
    cudaFuncSetAttribute(dot_relu_attn_v3,
                         cudaFuncAttributeMaxDynamicSharedMemorySize, SMEM_BYTES);
    dim3 grid(SEQ / BM, 16);
    dot_relu_attn_v3<<<grid, NTH, SMEM_BYTES>>>(q, k, v, o);
}

// round 6
// speedup vs baseline: 1.2133x; 1.0350x over previous
#include <cuda_runtime.h>
#include <cstdint>

// DotReluAttention: out = relu(Q @ K^T / 64) @ V ; B=2,H=8,S=4096,D=64 fp32.
// v4: 512 threads (16 warps, M=16/warp), BM=256, BN=128. Same verified smem
// layouts as v3. Split-accumulator GEMM1; P fed as truncated fp32 (no cvt),
// bias corrected in the output scale. Goal: 4 warps/SMSP latency hiding.

#define SEQ 4096
#define HD  64
#define BM  256
#define BN  128
#define NTH 512
#define NITER  (SEQ/BN)
#define NCHUNK (BN/8)

// smem layout (32-bit words) — identical to v3
#define PSTR 72
#define KSTR 72
#define VSTR 136
#define KOFF (BM*PSTR)
#define VOFF (KOFF + BN*KSTR)
#define SMEM_WORDS (VOFF + (BN/2)*VSTR)
#define SMEM_BYTES (SMEM_WORDS*4)       // 145408

// output scale: 1/64 times (1 + 2^-11) P-truncation bias correction
#define OSCALE (0.015625f * (1.0f + 4.8828125e-4f))

__device__ __forceinline__ uint32_t f2tf32(float f) {
    uint32_t r; asm("cvt.rna.tf32.f32 %0, %1;" : "=r"(r) : "f"(f)); return r;
}

__device__ __forceinline__ void mma8(float* c, const uint32_t* a,
                                     uint32_t b0, uint32_t b1) {
    asm volatile(
        "mma.sync.aligned.m16n8k8.row.col.f32.tf32.tf32.f32 "
        "{%0,%1,%2,%3}, {%4,%5,%6,%7}, {%8,%9}, {%0,%1,%2,%3};\n"
        : "+f"(c[0]), "+f"(c[1]), "+f"(c[2]), "+f"(c[3])
        : "r"(a[0]), "r"(a[1]), "r"(a[2]), "r"(a[3]), "r"(b0), "r"(b1));
}

__global__ __launch_bounds__(NTH, 1)
void dot_relu_attn_v4(const float* __restrict__ Q, const float* __restrict__ K,
                      const float* __restrict__ V, float* __restrict__ O) {
    extern __shared__ uint32_t sm[];
    uint32_t* sP = sm;           // [BM][PSTR]   P tile (Q staging first)
    uint32_t* sK = sm + KOFF;    // [BN][KSTR]
    uint32_t* sV = sm + VOFF;    // [BN/2][VSTR]

    const int tid  = threadIdx.x;
    const int warp = tid >> 5;
    const int lane = tid & 31;
    const int gid  = lane >> 2;
    const int tig  = lane & 3;
    const int m0   = warp * 16;     // warp owns 16 q rows

    const int bh = blockIdx.y;
    const int qb = blockIdx.x * BM;
    const float* Qp = Q + ((size_t)bh * SEQ + qb) * HD;
    const float* Kp = K + (size_t)bh * SEQ * HD;
    const float* Vp = V + (size_t)bh * SEQ * HD;
    float*       Op = O + ((size_t)bh * SEQ + qb) * HD;

    // ---- Stage Q (BM x 64, tf32-rna, pair-permuted k) ----
    #pragma unroll
    for (int i = 0; i < 8; i++) {
        int lin = tid + i * NTH;              // 4096 float4
        int row = lin >> 4, c4 = lin & 15;
        float4 v = *(const float4*)(Qp + row * HD + c4 * 4);
        uint32_t* d = &sP[row * PSTR + (c4 >> 1) * 8 + (c4 & 1)];
        d[0] = f2tf32(v.x); d[2] = f2tf32(v.y);
        d[4] = f2tf32(v.z); d[6] = f2tf32(v.w);
    }
    __syncthreads();

    // ---- Q A-fragments (LDS.64 pairs) ----
    uint32_t qa[8][4];
    #pragma unroll
    for (int kt = 0; kt < 8; kt++) {
        const uint32_t* p = &sP[(m0 + gid) * PSTR + kt * 8 + 2 * tig];
        uint2 lo = *(const uint2*)p;
        uint2 hi = *(const uint2*)(p + 8 * PSTR);
        qa[kt][0] = lo.x; qa[kt][1] = hi.x;
        qa[kt][2] = lo.y; qa[kt][3] = hi.y;
    }
    __syncthreads();   // sP now reused for P tiles

    float oacc[8][4];
    #pragma unroll
    for (int b = 0; b < 8; b++)
        #pragma unroll
        for (int c = 0; c < 4; c++) oacc[b][c] = 0.f;

    const int pp0 = 2 * ((2 * tig)     & 3) + ((2 * tig)     >> 2);
    const int pp1 = 2 * ((2 * tig + 1) & 3) + ((2 * tig + 1) >> 2);

    #pragma unroll 1
    for (int it = 0; it < NITER; it++) {
        const float* Kt = Kp + (size_t)it * BN * HD;
        const float* Vt = Vp + (size_t)it * BN * HD;

        // ---- Load K,V tiles (each BN x 64), permuted layouts ----
        #pragma unroll
        for (int i = 0; i < 4; i++) {
            int lin = tid + i * NTH;          // 2048 float4 per tensor
            int row = lin >> 4, c4 = lin & 15;
            float4 kv = *(const float4*)(Kt + row * HD + c4 * 4);
            uint32_t* dk = &sK[row * KSTR + (c4 >> 1) * 8 + (c4 & 1)];
            dk[0] = f2tf32(kv.x); dk[2] = f2tf32(kv.y);
            dk[4] = f2tf32(kv.z); dk[6] = f2tf32(kv.w);
            float4 vv = *(const float4*)(Vt + row * HD + c4 * 4);
            uint32_t* dv = &sV[((row >> 3) * 4 + (row & 3)) * VSTR
                               + c4 * 8 + ((row >> 2) & 1)];
            dv[0] = f2tf32(vv.x); dv[2] = f2tf32(vv.y);
            dv[4] = f2tf32(vv.z); dv[6] = f2tf32(vv.w);
        }
        __syncthreads();

        // ---- Fused chunk loop ----
        #pragma unroll 2
        for (int nk = 0; nk < NCHUNK; nk++) {
            // GEMM1: two independent accumulator chains
            float sa[4] = {0.f, 0.f, 0.f, 0.f};
            float sb[4] = {0.f, 0.f, 0.f, 0.f};
            const uint32_t* kb = &sK[(nk * 8 + gid) * KSTR + 2 * tig];
            #pragma unroll
            for (int kt = 0; kt < 4; kt++) {
                uint2 b = *(const uint2*)(kb + kt * 8);
                mma8(sa, qa[kt], b.x, b.y);
            }
            #pragma unroll
            for (int kt = 4; kt < 8; kt++) {
                uint2 b = *(const uint2*)(kb + kt * 8);
                mma8(sb, qa[kt], b.x, b.y);
            }
            // relu -> truncated-tf32 P write (own rows; permuted columns)
            uint32_t* pw = &sP[(m0 + gid) * PSTR + nk * 8];
            pw[pp0]            = __float_as_uint(fmaxf(sa[0] + sb[0], 0.f));
            pw[pp1]            = __float_as_uint(fmaxf(sa[1] + sb[1], 0.f));
            pw[8 * PSTR + pp0] = __float_as_uint(fmaxf(sa[2] + sb[2], 0.f));
            pw[8 * PSTR + pp1] = __float_as_uint(fmaxf(sa[3] + sb[3], 0.f));
            __syncwarp();

            // GEMM2: A fragment from P, 8 independent accumulators
            uint32_t pa[4];
            {
                const uint32_t* pr = &sP[(m0 + gid) * PSTR + nk * 8 + 2 * tig];
                uint2 lo = *(const uint2*)pr;
                uint2 hi = *(const uint2*)(pr + 8 * PSTR);
                pa[0] = lo.x; pa[1] = hi.x; pa[2] = lo.y; pa[3] = hi.y;
            }
            const uint32_t* vb = &sV[(nk * 4 + tig) * VSTR + gid * 2];
            #pragma unroll
            for (int n2 = 0; n2 < 8; n2++) {
                uint2 b = *(const uint2*)(vb + n2 * 16);
                mma8(oacc[n2], pa, b.x, b.y);
            }
        }
        __syncthreads();
    }

    // ---- Epilogue: O_out = O * (1/64)*(1+2^-11) ----
    {
        float* r0 = Op + (size_t)(m0 + gid) * HD;
        float* r1 = r0 + 8 * HD;
        #pragma unroll
        for (int n2 = 0; n2 < 8; n2++) {
            int col = n2 * 8 + 2 * tig;
            *(float2*)(r0 + col) = make_float2(oacc[n2][0] * OSCALE,
                                               oacc[n2][1] * OSCALE);
            *(float2*)(r1 + col) = make_float2(oacc[n2][2] * OSCALE,
                                               oacc[n2][3] * OSCALE);
        }
    }
}

extern "C" void kernel_launch(void* const* d_in, const int* in_sizes, int n_in,
                              void* d_out, int out_size) {
    const float* q = (const float*)d_in[0];
    const float* k = (const float*)d_in[1];
    const float* v = (const float*)d_in[2];
    float* o = (float*)d_out;
    cudaFuncSetAttribute(dot_relu_attn_v4,
                         cudaFuncAttributeMaxDynamicSharedMemorySize, SMEM_BYTES);
    dim3 grid(SEQ / BM, 16);
    dot_relu_attn_v4<<<grid, NTH, SMEM_BYTES>>>(q, k, v, o);
}

// round 7
// speedup vs baseline: 1.2252x; 1.0098x over previous
#include <cuda_runtime.h>
#include <cstdint>

// DotReluAttention: out = relu(Q @ K^T / 64) @ V ; B=2,H=8,S=4096,D=64 fp32.
// v5: warp-specialized. Warps 0-7 produce P = relu(Q K^T) at M=32/warp;
// warps 8-15 consume P with V (previous iter) at M=32/warp. P and V double
// buffered; 2 bar.sync per iter. Cuts B-fragment smem traffic ~40% vs v4.

#define SEQ 4096
#define HD  64
#define BM  256
#define BN  64
#define NTH 512
#define NITER  (SEQ/BN)   // 64
#define NCHUNK (BN/8)     // 8

// smem layout (32-bit words)
#define PSTR 72
#define KSTR 72
#define VSTR 136
#define PBUF  (BM*PSTR)          // 18432 words per P buffer
#define KOFF  (2*PBUF)           // 36864
#define VOFF  (KOFF + BN*KSTR)   // 41472
#define VHALF ((BN/2)*VSTR)      // 4352
#define SMEM_WORDS (VOFF + 2*VHALF)
#define SMEM_BYTES (SMEM_WORDS*4)   // 200704

// output scale: 1/64 times (1 + 2^-11) P-truncation bias correction
#define OSCALE (0.015625f * (1.0f + 4.8828125e-4f))

__device__ __forceinline__ uint32_t f2tf32(float f) {
    uint32_t r; asm("cvt.rna.tf32.f32 %0, %1;" : "=r"(r) : "f"(f)); return r;
}
__device__ __forceinline__ void mma8(float* c, const uint32_t* a,
                                     uint32_t b0, uint32_t b1) {
    asm volatile(
        "mma.sync.aligned.m16n8k8.row.col.f32.tf32.tf32.f32 "
        "{%0,%1,%2,%3}, {%4,%5,%6,%7}, {%8,%9}, {%0,%1,%2,%3};\n"
        : "+f"(c[0]), "+f"(c[1]), "+f"(c[2]), "+f"(c[3])
        : "r"(a[0]), "r"(a[1]), "r"(a[2]), "r"(a[3]), "r"(b0), "r"(b1));
}
#define BAR() asm volatile("bar.sync 0;" ::: "memory")

// cooperative K/V tile load for iteration it (all 512 threads)
__device__ __forceinline__ void load_tiles(uint32_t* sK, uint32_t* sV,
                                           const float* Kt, const float* Vt,
                                           int tid) {
    #pragma unroll
    for (int i = 0; i < 2; i++) {
        int lin = tid + i * NTH;            // 1024 float4 per tensor
        int row = lin >> 4, c4 = lin & 15;
        float4 kv = *(const float4*)(Kt + row * HD + c4 * 4);
        uint32_t* dk = &sK[row * KSTR + (c4 >> 1) * 8 + (c4 & 1)];
        dk[0] = f2tf32(kv.x); dk[2] = f2tf32(kv.y);
        dk[4] = f2tf32(kv.z); dk[6] = f2tf32(kv.w);
        float4 vv = *(const float4*)(Vt + row * HD + c4 * 4);
        uint32_t* dv = &sV[((row >> 3) * 4 + (row & 3)) * VSTR
                           + c4 * 8 + ((row >> 2) & 1)];
        dv[0] = f2tf32(vv.x); dv[2] = f2tf32(vv.y);
        dv[4] = f2tf32(vv.z); dv[6] = f2tf32(vv.w);
    }
}

__global__ __launch_bounds__(NTH, 1)
void dot_relu_attn_v5(const float* __restrict__ Q, const float* __restrict__ K,
                      const float* __restrict__ V, float* __restrict__ O) {
    extern __shared__ uint32_t sm[];
    uint32_t* sK = sm + KOFF;

    const int tid  = threadIdx.x;
    const int warp = tid >> 5;
    const int lane = tid & 31;
    const int gid  = lane >> 2;
    const int tig  = lane & 3;

    const int bh = blockIdx.y;
    const int qb = blockIdx.x * BM;
    const float* Qp = Q + ((size_t)bh * SEQ + qb) * HD;
    const float* Kp = K + (size_t)bh * SEQ * HD;
    const float* Vp = V + (size_t)bh * SEQ * HD;
    float*       Op = O + ((size_t)bh * SEQ + qb) * HD;

    // ---- Stage Q into P-buffer 0 (tf32-rna, pair-permuted) ----
    #pragma unroll
    for (int i = 0; i < 8; i++) {
        int lin = tid + i * NTH;              // 4096 float4
        int row = lin >> 4, c4 = lin & 15;
        float4 v = *(const float4*)(Qp + row * HD + c4 * 4);
        uint32_t* d = &sm[row * PSTR + (c4 >> 1) * 8 + (c4 & 1)];
        d[0] = f2tf32(v.x); d[2] = f2tf32(v.y);
        d[4] = f2tf32(v.z); d[6] = f2tf32(v.w);
    }
    __syncthreads();

    if (warp < 8) {
        // ================= G1: producers (S = relu(Q K^T)) =================
        const int m0 = warp * 32;
        uint32_t qa[8][2][4];
        #pragma unroll
        for (int kt = 0; kt < 8; kt++)
            #pragma unroll
            for (int mt = 0; mt < 2; mt++) {
                const uint32_t* p = &sm[(m0 + mt * 16 + gid) * PSTR + kt * 8 + 2 * tig];
                uint2 lo = *(const uint2*)p;
                uint2 hi = *(const uint2*)(p + 8 * PSTR);
                qa[kt][mt][0] = lo.x; qa[kt][mt][1] = hi.x;
                qa[kt][mt][2] = lo.y; qa[kt][mt][3] = hi.y;
            }
        const int pp0 = 2 * ((2 * tig)     & 3) + ((2 * tig)     >> 2);
        const int pp1 = 2 * ((2 * tig + 1) & 3) + ((2 * tig + 1) >> 2);

        #pragma unroll 1
        for (int it = 0; it < NITER; it++) {
            load_tiles(sK, sm + VOFF + (it & 1) * VHALF,
                       Kp + (size_t)it * BN * HD, Vp + (size_t)it * BN * HD, tid);
            BAR();
            uint32_t* sP = sm + (it & 1) * PBUF;
            #pragma unroll 2
            for (int nk = 0; nk < NCHUNK; nk++) {
                uint2 bc[8];
                const uint32_t* kb = &sK[(nk * 8 + gid) * KSTR + 2 * tig];
                #pragma unroll
                for (int kt = 0; kt < 8; kt++) bc[kt] = *(const uint2*)(kb + kt * 8);
                #pragma unroll
                for (int mt = 0; mt < 2; mt++) {
                    float sa[4] = {0.f, 0.f, 0.f, 0.f};
                    float sb[4] = {0.f, 0.f, 0.f, 0.f};
                    #pragma unroll
                    for (int kt = 0; kt < 4; kt++) mma8(sa, qa[kt][mt], bc[kt].x, bc[kt].y);
                    #pragma unroll
                    for (int kt = 4; kt < 8; kt++) mma8(sb, qa[kt][mt], bc[kt].x, bc[kt].y);
                    uint32_t* pw = &sP[(m0 + mt * 16 + gid) * PSTR + nk * 8];
                    pw[pp0]            = __float_as_uint(fmaxf(sa[0] + sb[0], 0.f));
                    pw[pp1]            = __float_as_uint(fmaxf(sa[1] + sb[1], 0.f));
                    pw[8 * PSTR + pp0] = __float_as_uint(fmaxf(sa[2] + sb[2], 0.f));
                    pw[8 * PSTR + pp1] = __float_as_uint(fmaxf(sa[3] + sb[3], 0.f));
                }
            }
            BAR();
        }
    } else {
        // ================= G2: consumers (O += P V) =================
        const int m0 = (warp - 8) * 32;
        float oacc[2][8][4];
        #pragma unroll
        for (int a = 0; a < 2; a++)
            #pragma unroll
            for (int b = 0; b < 8; b++)
                #pragma unroll
                for (int c = 0; c < 4; c++) oacc[a][b][c] = 0.f;

        #pragma unroll 1
        for (int it = 0; it < NITER; it++) {
            load_tiles(sK, sm + VOFF + (it & 1) * VHALF,
                       Kp + (size_t)it * BN * HD, Vp + (size_t)it * BN * HD, tid);
            BAR();
            if (it >= 1) {
                const uint32_t* sP = sm + ((it - 1) & 1) * PBUF;
                const uint32_t* sV = sm + VOFF + ((it - 1) & 1) * VHALF;
                #pragma unroll 2
                for (int nk = 0; nk < NCHUNK; nk++) {
                    uint32_t pa[2][4];
                    #pragma unroll
                    for (int mt = 0; mt < 2; mt++) {
                        const uint32_t* pr = &sP[(m0 + mt * 16 + gid) * PSTR + nk * 8 + 2 * tig];
                        uint2 lo = *(const uint2*)pr;
                        uint2 hi = *(const uint2*)(pr + 8 * PSTR);
                        pa[mt][0] = lo.x; pa[mt][1] = hi.x;
                        pa[mt][2] = lo.y; pa[mt][3] = hi.y;
                    }
                    const uint32_t* vb = &sV[(nk * 4 + tig) * VSTR + gid * 2];
                    #pragma unroll
                    for (int n2 = 0; n2 < 8; n2++) {
                        uint2 b = *(const uint2*)(vb + n2 * 16);
                        mma8(oacc[0][n2], pa[0], b.x, b.y);
                        mma8(oacc[1][n2], pa[1], b.x, b.y);
                    }
                }
            }
            BAR();
        }
        // final (drain) iteration: consume P/V of it = NITER-1
        {
            const uint32_t* sP = sm + ((NITER - 1) & 1) * PBUF;
            const uint32_t* sV = sm + VOFF + ((NITER - 1) & 1) * VHALF;
            #pragma unroll 2
            for (int nk = 0; nk < NCHUNK; nk++) {
                uint32_t pa[2][4];
                #pragma unroll
                for (int mt = 0; mt < 2; mt++) {
                    const uint32_t* pr = &sP[(m0 + mt * 16 + gid) * PSTR + nk * 8 + 2 * tig];
                    uint2 lo = *(const uint2*)pr;
                    uint2 hi = *(const uint2*)(pr + 8 * PSTR);
                    pa[mt][0] = lo.x; pa[mt][1] = hi.x;
                    pa[mt][2] = lo.y; pa[mt][3] = hi.y;
                }
                const uint32_t* vb = &sV[(nk * 4 + tig) * VSTR + gid * 2];
                #pragma unroll
                for (int n2 = 0; n2 < 8; n2++) {
                    uint2 b = *(const uint2*)(vb + n2 * 16);
                    mma8(oacc[0][n2], pa[0], b.x, b.y);
                    mma8(oacc[1][n2], pa[1], b.x, b.y);
                }
            }
        }
        // epilogue
        #pragma unroll
        for (int mt = 0; mt < 2; mt++) {
            float* r0 = Op + (size_t)(m0 + mt * 16 + gid) * HD;
            float* r1 = r0 + 8 * HD;
            #pragma unroll
            for (int n2 = 0; n2 < 8; n2++) {
                int col = n2 * 8 + 2 * tig;
                *(float2*)(r0 + col) = make_float2(oacc[mt][n2][0] * OSCALE,
                                                   oacc[mt][n2][1] * OSCALE);
                *(float2*)(r1 + col) = make_float2(oacc[mt][n2][2] * OSCALE,
                                                   oacc[mt][n2][3] * OSCALE);
            }
        }
    }
}

extern "C" void kernel_launch(void* const* d_in, const int* in_sizes, int n_in,
                              void* d_out, int out_size) {
    const float* q = (const float*)d_in[0];
    const float* k = (const float*)d_in[1];
    const float* v = (const float*)d_in[2];
    float* o = (float*)d_out;
    cudaFuncSetAttribute(dot_relu_attn_v5,
                         cudaFuncAttributeMaxDynamicSharedMemorySize, SMEM_BYTES);
    dim3 grid(SEQ / BM, 16);
    dot_relu_attn_v5<<<grid, NTH, SMEM_BYTES>>>(q, k, v, o);
}

// round 9
// speedup vs baseline: 2.4354x; 1.9878x over previous
#include <cuda_runtime.h>
#include <cuda_fp16.h>
#include <cstdint>

// DotReluAttention: out = relu(Q @ K^T / 64) @ V ; B=2,H=8,S=4096,D=64 fp32.
// v6: fp16 m16n8k16 MMAs (11-bit mantissa == tf32 precision, 2x FLOP/instr).
// 512 threads, 16 warps x 16 q-rows, BM=256, BN=128. fp32 accumulation.

#define SEQ 4096
#define HD  64
#define BM  256
#define BN  128
#define NTH 512
#define NITER (SEQ/BN)    // 32
#define NK16  (BN/16)     // 8 k16-chunks per tile (GEMM2); 2 G1 chunks each

// smem layout (32-bit words)
#define PSTR 72   // P rows: 64 half2 words + 8 pad (also Q staging, 32 words)
#define KSTR 40   // K rows: 32 half2 words + 8 pad
#define VSTR 72   // V pair-rows: 64 half2 words + 8 pad
#define KOFF (BM*PSTR)                    // 18432
#define VOFF (KOFF + BN*KSTR)             // 23552
#define SMEM_WORDS (VOFF + (BN/2)*VSTR)   // 28160
#define SMEM_BYTES (SMEM_WORDS*4)         // 112640

__device__ __forceinline__ uint32_t pack2(float a, float b) {
    __half2 h = __floats2half2_rn(a, b);
    return *reinterpret_cast<uint32_t*>(&h);
}

__device__ __forceinline__ void mma16(float* c, const uint32_t* a,
                                      uint32_t b0, uint32_t b1) {
    asm volatile(
        "mma.sync.aligned.m16n8k16.row.col.f32.f16.f16.f32 "
        "{%0,%1,%2,%3}, {%4,%5,%6,%7}, {%8,%9}, {%0,%1,%2,%3};\n"
        : "+f"(c[0]), "+f"(c[1]), "+f"(c[2]), "+f"(c[3])
        : "r"(a[0]), "r"(a[1]), "r"(a[2]), "r"(a[3]), "r"(b0), "r"(b1));
}

// word w -> pair-permuted position (within each 8-word k16 chunk: j -> 2(j&3)+(j>>2))
__device__ __forceinline__ int wpos(int w) {
    return (w & ~7) + 2 * (w & 3) + ((w & 4) >> 2);
}

__global__ __launch_bounds__(NTH, 1)
void dot_relu_attn_v6(const float* __restrict__ Q, const float* __restrict__ K,
                      const float* __restrict__ V, float* __restrict__ O) {
    extern __shared__ uint32_t sm[];
    uint32_t* sP = sm;           // [BM][PSTR]  P tile (Q staging first)
    uint32_t* sK = sm + KOFF;    // [BN][KSTR]
    uint32_t* sV = sm + VOFF;    // [BN/2][VSTR] packed vertical kv-pairs

    const int tid  = threadIdx.x;
    const int warp = tid >> 5;
    const int lane = tid & 31;
    const int gid  = lane >> 2;
    const int tig  = lane & 3;
    const int m0   = warp * 16;

    const int bh = blockIdx.y;
    const int qb = blockIdx.x * BM;
    const float* Qp = Q + ((size_t)bh * SEQ + qb) * HD;
    const float* Kp = K + (size_t)bh * SEQ * HD;
    const float* Vp = V + (size_t)bh * SEQ * HD;
    float*       Op = O + ((size_t)bh * SEQ + qb) * HD;

    // ---- Stage Q (BM x 64 -> half2 words, pair-permuted per k16 chunk) ----
    #pragma unroll
    for (int i = 0; i < 8; i++) {
        int lin = tid + i * NTH;              // 4096 float4
        int row = lin >> 4, c4 = lin & 15;
        float4 v = *(const float4*)(Qp + row * HD + c4 * 4);
        sP[row * PSTR + wpos(2 * c4)]     = pack2(v.x, v.y);
        sP[row * PSTR + wpos(2 * c4 + 1)] = pack2(v.z, v.w);
    }
    __syncthreads();

    // ---- Q A-fragments: 4 k16 chunks (LDS.64 pairs) ----
    uint32_t qa[4][4];
    #pragma unroll
    for (int kt = 0; kt < 4; kt++) {
        const uint32_t* p = &sP[(m0 + gid) * PSTR + kt * 8 + 2 * tig];
        uint2 lo = *(const uint2*)p;            // {a0, a2}
        uint2 hi = *(const uint2*)(p + 8 * PSTR); // {a1, a3}
        qa[kt][0] = lo.x; qa[kt][1] = hi.x;
        qa[kt][2] = lo.y; qa[kt][3] = hi.y;
    }
    __syncthreads();   // sP now reused for P tiles

    float oacc[8][4];
    #pragma unroll
    for (int b = 0; b < 8; b++)
        #pragma unroll
        for (int c = 0; c < 4; c++) oacc[b][c] = 0.f;

    #pragma unroll 1
    for (int it = 0; it < NITER; it++) {
        const float* Kt = Kp + (size_t)it * BN * HD;
        const float* Vt = Vp + (size_t)it * BN * HD;

        // ---- Load K tile (BN x 64) ----
        #pragma unroll
        for (int i = 0; i < 4; i++) {
            int lin = tid + i * NTH;          // 2048 float4
            int row = lin >> 4, c4 = lin & 15;
            float4 kv = *(const float4*)(Kt + row * HD + c4 * 4);
            sK[row * KSTR + wpos(2 * c4)]     = pack2(kv.x, kv.y);
            sK[row * KSTR + wpos(2 * c4 + 1)] = pack2(kv.z, kv.w);
        }
        // ---- Load V tile (BN x 64, packed vertical kv pairs: word = {V[2p][n],V[2p+1][n]}) ----
        #pragma unroll
        for (int i = 0; i < 2; i++) {
            int lin = tid + i * NTH;          // 1024 2x4 blocks
            int pr = lin >> 4, c4 = lin & 15;
            float4 r0 = *(const float4*)(Vt + (2 * pr)     * HD + c4 * 4);
            float4 r1 = *(const float4*)(Vt + (2 * pr + 1) * HD + c4 * 4);
            uint32_t* dv = &sV[pr * VSTR + c4 * 4];
            dv[0] = pack2(r0.x, r1.x); dv[1] = pack2(r0.y, r1.y);
            dv[2] = pack2(r0.z, r1.z); dv[3] = pack2(r0.w, r1.w);
        }
        __syncthreads();

        // ---- Fused loop over 8 k16-chunks ----
        #pragma unroll 2
        for (int nk = 0; nk < NK16; nk++) {
            // GEMM1: two 8-col chunks (h=0,1), 4 MMAs each (split accumulators)
            #pragma unroll
            for (int h = 0; h < 2; h++) {
                const int n8 = 2 * nk + h;
                const uint32_t* kb = &sK[(n8 * 8 + gid) * KSTR + 2 * tig];
                uint2 b0 = *(const uint2*)(kb);
                uint2 b1 = *(const uint2*)(kb + 8);
                uint2 b2 = *(const uint2*)(kb + 16);
                uint2 b3 = *(const uint2*)(kb + 24);
                float sa[4] = {0.f, 0.f, 0.f, 0.f};
                float sb[4] = {0.f, 0.f, 0.f, 0.f};
                mma16(sa, qa[0], b0.x, b0.y);
                mma16(sb, qa[1], b1.x, b1.y);
                mma16(sa, qa[2], b2.x, b2.y);
                mma16(sb, qa[3], b3.x, b3.y);
                // relu -> half2 P write (pair-permuted: pos = nk*8 + 2*tig + h)
                uint32_t* pw = &sP[(m0 + gid) * PSTR + nk * 8 + 2 * tig + h];
                pw[0]        = pack2(fmaxf(sa[0] + sb[0], 0.f),
                                     fmaxf(sa[1] + sb[1], 0.f));
                pw[8 * PSTR] = pack2(fmaxf(sa[2] + sb[2], 0.f),
                                     fmaxf(sa[3] + sb[3], 0.f));
            }
            __syncwarp();

            // GEMM2: A from P (LDS.64), B from packed V (2x LDS.32), 8 indep MMAs
            uint32_t pa[4];
            {
                const uint32_t* pr_ = &sP[(m0 + gid) * PSTR + nk * 8 + 2 * tig];
                uint2 lo = *(const uint2*)pr_;
                uint2 hi = *(const uint2*)(pr_ + 8 * PSTR);
                pa[0] = lo.x; pa[1] = hi.x; pa[2] = lo.y; pa[3] = hi.y;
            }
            const uint32_t* vb = &sV[(8 * nk + tig) * VSTR + gid];
            #pragma unroll
            for (int n2 = 0; n2 < 8; n2++) {
                uint32_t b0 = vb[n2 * 8];
                uint32_t b1 = vb[4 * VSTR + n2 * 8];
                mma16(oacc[n2], pa, b0, b1);
            }
        }
        __syncthreads();
    }

    // ---- Epilogue: O_out = O / 64 (exact; P was rne-rounded, no bias) ----
    {
        float* r0 = Op + (size_t)(m0 + gid) * HD;
        float* r1 = r0 + 8 * HD;
        #pragma unroll
        for (int n2 = 0; n2 < 8; n2++) {
            int col = n2 * 8 + 2 * tig;
            *(float2*)(r0 + col) = make_float2(oacc[n2][0] * 0.015625f,
                                               oacc[n2][1] * 0.015625f);
            *(float2*)(r1 + col) = make_float2(oacc[n2][2] * 0.015625f,
                                               oacc[n2][3] * 0.015625f);
        }
    }
}

extern "C" void kernel_launch(void* const* d_in, const int* in_sizes, int n_in,
                              void* d_out, int out_size) {
    const float* q = (const float*)d_in[0];
    const float* k = (const float*)d_in[1];
    const float* v = (const float*)d_in[2];
    float* o = (float*)d_out;
    cudaFuncSetAttribute(dot_relu_attn_v6,
                         cudaFuncAttributeMaxDynamicSharedMemorySize, SMEM_BYTES);
    dim3 grid(SEQ / BM, 16);
    dot_relu_attn_v6<<<grid, NTH, SMEM_BYTES>>>(q, k, v, o);
}

// round 10
// speedup vs baseline: 2.7420x; 1.1259x over previous
#include <cuda_runtime.h>
#include <cuda_fp16.h>
#include <cstdint>

// DotReluAttention: out = relu(Q @ K^T / 64) @ V ; B=2,H=8,S=4096,D=64 fp32.
// v7: fp16 m16n8k16, P round-trip ELIMINATED -- GEMM1 C-fragments are
// reused directly (relu+pack in registers) as GEMM2 A-fragments.
// 512 threads, 16 warps x 16 q-rows, BM=256, BN=128, fp32 accumulation.

#define SEQ 4096
#define HD  64
#define BM  256
#define BN  128
#define NTH 512
#define NITER (SEQ/BN)    // 32
#define NK16  (BN/16)     // 8 k16-chunks per tile

// smem layout (32-bit words)
#define QSTR 40   // Q staging rows: 32 half2 words + 8 pad (startup only)
#define KSTR 40   // K rows: 32 half2 words + 8 pad
#define VSTR 72   // V pair-rows: 64 half2 words + 8 pad
#define VOFF (BN*KSTR)                    // 5120 (K tile first)
#define SMEM_WORDS (BM*QSTR)              // 10240 (staging superset of K+V=9728)
#define SMEM_BYTES (SMEM_WORDS*4)         // 40960

__device__ __forceinline__ uint32_t pack2(float a, float b) {
    __half2 h = __floats2half2_rn(a, b);
    return *reinterpret_cast<uint32_t*>(&h);
}

__device__ __forceinline__ void mma16(float* c, const uint32_t* a,
                                      uint32_t b0, uint32_t b1) {
    asm volatile(
        "mma.sync.aligned.m16n8k16.row.col.f32.f16.f16.f32 "
        "{%0,%1,%2,%3}, {%4,%5,%6,%7}, {%8,%9}, {%0,%1,%2,%3};\n"
        : "+f"(c[0]), "+f"(c[1]), "+f"(c[2]), "+f"(c[3])
        : "r"(a[0]), "r"(a[1]), "r"(a[2]), "r"(a[3]), "r"(b0), "r"(b1));
}

// word w -> pair-permuted position (within each 8-word chunk: j -> 2(j&3)+(j>>2))
__device__ __forceinline__ int wpos(int w) {
    return (w & ~7) + 2 * (w & 3) + ((w & 4) >> 2);
}

__global__ __launch_bounds__(NTH, 1)
void dot_relu_attn_v7(const float* __restrict__ Q, const float* __restrict__ K,
                      const float* __restrict__ V, float* __restrict__ O) {
    extern __shared__ uint32_t sm[];
    uint32_t* sK = sm;           // [BN][KSTR]       (also Q staging, stride QSTR)
    uint32_t* sV = sm + VOFF;    // [BN/2][VSTR] packed vertical kv-pairs

    const int tid  = threadIdx.x;
    const int warp = tid >> 5;
    const int lane = tid & 31;
    const int gid  = lane >> 2;
    const int tig  = lane & 3;
    const int m0   = warp * 16;

    const int bh = blockIdx.y;
    const int qb = blockIdx.x * BM;
    const float* Qp = Q + ((size_t)bh * SEQ + qb) * HD;
    const float* Kp = K + (size_t)bh * SEQ * HD;
    const float* Vp = V + (size_t)bh * SEQ * HD;
    float*       Op = O + ((size_t)bh * SEQ + qb) * HD;

    // ---- Stage Q (BM x 64 -> half2 words, pair-permuted per k16 chunk) ----
    #pragma unroll
    for (int i = 0; i < 8; i++) {
        int lin = tid + i * NTH;              // 4096 float4
        int row = lin >> 4, c4 = lin & 15;
        float4 v = *(const float4*)(Qp + row * HD + c4 * 4);
        sm[row * QSTR + wpos(2 * c4)]     = pack2(v.x, v.y);
        sm[row * QSTR + wpos(2 * c4 + 1)] = pack2(v.z, v.w);
    }
    __syncthreads();

    // ---- Q A-fragments: 4 k16 chunks (LDS.64 pairs) ----
    uint32_t qa[4][4];
    #pragma unroll
    for (int kt = 0; kt < 4; kt++) {
        const uint32_t* p = &sm[(m0 + gid) * QSTR + kt * 8 + 2 * tig];
        uint2 lo = *(const uint2*)p;              // {a0, a2}
        uint2 hi = *(const uint2*)(p + 8 * QSTR); // {a1, a3}
        qa[kt][0] = lo.x; qa[kt][1] = hi.x;
        qa[kt][2] = lo.y; qa[kt][3] = hi.y;
    }
    __syncthreads();   // staging area now reused for K/V tiles

    float oacc[8][4];
    #pragma unroll
    for (int b = 0; b < 8; b++)
        #pragma unroll
        for (int c = 0; c < 4; c++) oacc[b][c] = 0.f;

    #pragma unroll 1
    for (int it = 0; it < NITER; it++) {
        const float* Kt = Kp + (size_t)it * BN * HD;
        const float* Vt = Vp + (size_t)it * BN * HD;

        // ---- Load K tile (BN x 64) ----
        #pragma unroll
        for (int i = 0; i < 4; i++) {
            int lin = tid + i * NTH;          // 2048 float4
            int row = lin >> 4, c4 = lin & 15;
            float4 kv = *(const float4*)(Kt + row * HD + c4 * 4);
            sK[row * KSTR + wpos(2 * c4)]     = pack2(kv.x, kv.y);
            sK[row * KSTR + wpos(2 * c4 + 1)] = pack2(kv.z, kv.w);
        }
        // ---- Load V tile (packed vertical kv pairs: word = {V[2p][n],V[2p+1][n]}) ----
        #pragma unroll
        for (int i = 0; i < 2; i++) {
            int lin = tid + i * NTH;          // 1024 2x4 blocks
            int pr = lin >> 4, c4 = lin & 15;
            float4 r0 = *(const float4*)(Vt + (2 * pr)     * HD + c4 * 4);
            float4 r1 = *(const float4*)(Vt + (2 * pr + 1) * HD + c4 * 4);
            uint32_t* dv = &sV[pr * VSTR + c4 * 4];
            dv[0] = pack2(r0.x, r1.x); dv[1] = pack2(r0.y, r1.y);
            dv[2] = pack2(r0.z, r1.z); dv[3] = pack2(r0.w, r1.w);
        }
        __syncthreads();

        // ---- Fused loop over 8 k16-chunks: G1 -> registers -> G2 ----
        #pragma unroll 2
        for (int nk = 0; nk < NK16; nk++) {
            // GEMM1: two 8-col halves; C-fragments become GEMM2 A-fragments
            float s0[4], s1[4];
            {   // half h=0 -> S cols 16nk+0..7
                const uint32_t* kb = &sK[((2 * nk) * 8 + gid) * KSTR + 2 * tig];
                uint2 b0 = *(const uint2*)(kb);
                uint2 b1 = *(const uint2*)(kb + 8);
                uint2 b2 = *(const uint2*)(kb + 16);
                uint2 b3 = *(const uint2*)(kb + 24);
                float ta[4] = {0.f, 0.f, 0.f, 0.f};
                float tb[4] = {0.f, 0.f, 0.f, 0.f};
                mma16(ta, qa[0], b0.x, b0.y);
                mma16(tb, qa[1], b1.x, b1.y);
                mma16(ta, qa[2], b2.x, b2.y);
                mma16(tb, qa[3], b3.x, b3.y);
                s0[0] = ta[0] + tb[0]; s0[1] = ta[1] + tb[1];
                s0[2] = ta[2] + tb[2]; s0[3] = ta[3] + tb[3];
            }
            {   // half h=1 -> S cols 16nk+8..15
                const uint32_t* kb = &sK[((2 * nk + 1) * 8 + gid) * KSTR + 2 * tig];
                uint2 b0 = *(const uint2*)(kb);
                uint2 b1 = *(const uint2*)(kb + 8);
                uint2 b2 = *(const uint2*)(kb + 16);
                uint2 b3 = *(const uint2*)(kb + 24);
                float ta[4] = {0.f, 0.f, 0.f, 0.f};
                float tb[4] = {0.f, 0.f, 0.f, 0.f};
                mma16(ta, qa[0], b0.x, b0.y);
                mma16(tb, qa[1], b1.x, b1.y);
                mma16(ta, qa[2], b2.x, b2.y);
                mma16(tb, qa[3], b3.x, b3.y);
                s1[0] = ta[0] + tb[0]; s1[1] = ta[1] + tb[1];
                s1[2] = ta[2] + tb[2]; s1[3] = ta[3] + tb[3];
            }
            // relu + pack: C(m16n8) -> A(m16n8k16) identity mapping
            uint32_t pa[4];
            pa[0] = pack2(fmaxf(s0[0], 0.f), fmaxf(s0[1], 0.f)); // row gid,   k=2tig
            pa[1] = pack2(fmaxf(s0[2], 0.f), fmaxf(s0[3], 0.f)); // row gid+8, k=2tig
            pa[2] = pack2(fmaxf(s1[0], 0.f), fmaxf(s1[1], 0.f)); // row gid,   k=2tig+8
            pa[3] = pack2(fmaxf(s1[2], 0.f), fmaxf(s1[3], 0.f)); // row gid+8, k=2tig+8

            // GEMM2: B from packed V (2x LDS.32), 8 independent accumulators
            const uint32_t* vb = &sV[(8 * nk + tig) * VSTR + gid];
            #pragma unroll
            for (int n2 = 0; n2 < 8; n2++) {
                uint32_t b0 = vb[n2 * 8];
                uint32_t b1 = vb[4 * VSTR + n2 * 8];
                mma16(oacc[n2], pa, b0, b1);
            }
        }
        __syncthreads();
    }

    // ---- Epilogue: O_out = O / 64 ----
    {
        float* r0 = Op + (size_t)(m0 + gid) * HD;
        float* r1 = r0 + 8 * HD;
        #pragma unroll
        for (int n2 = 0; n2 < 8; n2++) {
            int col = n2 * 8 + 2 * tig;
            *(float2*)(r0 + col) = make_float2(oacc[n2][0] * 0.015625f,
                                               oacc[n2][1] * 0.015625f);
            *(float2*)(r1 + col) = make_float2(oacc[n2][2] * 0.015625f,
                                               oacc[n2][3] * 0.015625f);
        }
    }
}

extern "C" void kernel_launch(void* const* d_in, const int* in_sizes, int n_in,
                              void* d_out, int out_size) {
    const float* q = (const float*)d_in[0];
    const float* k = (const float*)d_in[1];
    const float* v = (const float*)d_in[2];
    float* o = (float*)d_out;
    cudaFuncSetAttribute(dot_relu_attn_v7,
                         cudaFuncAttributeMaxDynamicSharedMemorySize, SMEM_BYTES);
    dim3 grid(SEQ / BM, 16);
    dot_relu_attn_v7<<<grid, NTH, SMEM_BYTES>>>(q, k, v, o);
}

// round 11
// speedup vs baseline: 3.0486x; 1.1118x over previous
#include <cuda_runtime.h>
#include <cuda_fp16.h>
#include <cstdint>

// DotReluAttention: out = relu(Q @ K^T / 64) @ V ; B=2,H=8,S=4096,D=64 fp32.
// v8: two kernels. (1) convert K,V fp32 -> fp16 in the exact permuted smem
// image. (2) fused attention (v7 compute) with cp.async double-buffered K/V
// tiles: load latency hidden under MMAs, no conversion in the hot loop.

#define SEQ 4096
#define HD  64
#define BM  256
#define BN  128
#define NTH 512
#define NITER (SEQ/BN)    // 32
#define NK16  (BN/16)     // 8
#define BH    16

// smem geometry (32-bit words)
#define QSTR 40           // Q staging rows (startup only)
#define KSTR 40           // K rows: 32 data words + 8 pad (160B, 16B-aligned)
#define VSTR 72           // V pair-rows: 64 data words + 8 pad (288B)
#define KWORDS (BN*KSTR)              // 5120
#define BUFW   (KWORDS + (BN/2)*VSTR) // 9728 words per buffer
#define SMEM_WORDS (2*BUFW)           // 19456 (Q staging 10240 fits inside)
#define SMEM_BYTES (SMEM_WORDS*4)     // 77824

// pre-converted fp16 images (packed half2 words)
__device__ __align__(16) uint32_t g_K16[(size_t)BH*SEQ*32];       // 8MB
__device__ __align__(16) uint32_t g_V16[(size_t)BH*(SEQ/2)*64];   // 8MB

__device__ __forceinline__ uint32_t pack2(float a, float b) {
    __half2 h = __floats2half2_rn(a, b);
    return *reinterpret_cast<uint32_t*>(&h);
}
__device__ __forceinline__ void mma16(float* c, const uint32_t* a,
                                      uint32_t b0, uint32_t b1) {
    asm volatile(
        "mma.sync.aligned.m16n8k16.row.col.f32.f16.f16.f32 "
        "{%0,%1,%2,%3}, {%4,%5,%6,%7}, {%8,%9}, {%0,%1,%2,%3};\n"
        : "+f"(c[0]), "+f"(c[1]), "+f"(c[2]), "+f"(c[3])
        : "r"(a[0]), "r"(a[1]), "r"(a[2]), "r"(a[3]), "r"(b0), "r"(b1));
}
__device__ __forceinline__ int wpos(int w) {    // pair-permute within 8-word chunk
    return (w & ~7) + 2 * (w & 3) + ((w & 4) >> 2);
}
__device__ __forceinline__ uint32_t smem_u32(const void* p) {
    uint32_t a;
    asm("{ .reg .u64 t; cvta.to.shared.u64 t, %1; cvt.u32.u64 %0, t; }" : "=r"(a) : "l"(p));
    return a;
}

// ---------------- kernel 1: fp32 -> packed fp16 images ----------------
__global__ __launch_bounds__(512)
void convert_kv(const float* __restrict__ K, const float* __restrict__ V) {
    int t = blockIdx.x * 512 + threadIdx.x;   // 0 .. 262143
    {   // K: row = global row (bh*SEQ+s), chunk j covers words 8j..8j+7
        int row = t >> 2, j = t & 3;
        const float4* src = (const float4*)(K + (size_t)row * HD + j * 16);
        float4 a = src[0], b = src[1], c = src[2], d = src[3];
        uint32_t* dst = g_K16 + (size_t)row * 32 + j * 8;
        dst[0] = pack2(a.x, a.y); dst[2] = pack2(a.z, a.w);
        dst[4] = pack2(b.x, b.y); dst[6] = pack2(b.z, b.w);
        dst[1] = pack2(c.x, c.y); dst[3] = pack2(c.z, c.w);
        dst[5] = pack2(d.x, d.y); dst[7] = pack2(d.z, d.w);
    }
    {   // V: pair-row pr, words n=8j..8j+7: word = {V[2pr][n], V[2pr+1][n]}
        int pr = t >> 3, j = t & 7;
        const float* s0 = V + (size_t)(2 * pr) * HD + j * 8;
        float4 r0a = ((const float4*)s0)[0], r0b = ((const float4*)s0)[1];
        float4 r1a = ((const float4*)(s0 + HD))[0], r1b = ((const float4*)(s0 + HD))[1];
        uint32_t* dst = g_V16 + (size_t)pr * 64 + j * 8;
        dst[0] = pack2(r0a.x, r1a.x); dst[1] = pack2(r0a.y, r1a.y);
        dst[2] = pack2(r0a.z, r1a.z); dst[3] = pack2(r0a.w, r1a.w);
        dst[4] = pack2(r0b.x, r1b.x); dst[5] = pack2(r0b.y, r1b.y);
        dst[6] = pack2(r0b.z, r1b.z); dst[7] = pack2(r0b.w, r1b.w);
    }
}

// issue cp.async copies for one K/V tile into smem buffer at byte addr sbuf
__device__ __forceinline__ void issue_tile(int bh, int it, uint32_t sbuf, int tid) {
    const char* kbase = (const char*)(g_K16 + ((size_t)bh * SEQ + it * BN) * 32);
    #pragma unroll
    for (int i = 0; i < 2; i++) {
        int c = tid + i * NTH;                 // 1024 chunks of 16B
        uint32_t dst = sbuf + (c >> 3) * (KSTR * 4) + (c & 7) * 16;
        asm volatile("cp.async.cg.shared.global [%0], [%1], 16;"
                     :: "r"(dst), "l"(kbase + c * 16) : "memory");
    }
    const char* vbase = (const char*)(g_V16 + ((size_t)bh * (SEQ/2) + it * (BN/2)) * 64);
    uint32_t svbuf = sbuf + KWORDS * 4;
    #pragma unroll
    for (int i = 0; i < 2; i++) {
        int c = tid + i * NTH;                 // 1024 chunks of 16B
        uint32_t dst = svbuf + (c >> 4) * (VSTR * 4) + (c & 15) * 16;
        asm volatile("cp.async.cg.shared.global [%0], [%1], 16;"
                     :: "r"(dst), "l"(vbase + c * 16) : "memory");
    }
}
#define CP_COMMIT() asm volatile("cp.async.commit_group;" ::: "memory")
#define CP_WAIT(n)  asm volatile("cp.async.wait_group %0;" :: "n"(n) : "memory")

// ---------------- kernel 2: fused attention ----------------
__global__ __launch_bounds__(NTH, 1)
void dot_relu_attn_v8(const float* __restrict__ Q, float* __restrict__ O) {
    extern __shared__ uint32_t sm[];
    const uint32_t sbase = smem_u32(sm);

    const int tid  = threadIdx.x;
    const int warp = tid >> 5;
    const int lane = tid & 31;
    const int gid  = lane >> 2;
    const int tig  = lane & 3;
    const int m0   = warp * 16;

    const int bh = blockIdx.y;
    const int qb = blockIdx.x * BM;
    const float* Qp = Q + ((size_t)bh * SEQ + qb) * HD;
    float*       Op = O + ((size_t)bh * SEQ + qb) * HD;

    // ---- Stage Q (one-time; staging area overlaps the K/V buffers) ----
    #pragma unroll
    for (int i = 0; i < 8; i++) {
        int lin = tid + i * NTH;
        int row = lin >> 4, c4 = lin & 15;
        float4 v = *(const float4*)(Qp + row * HD + c4 * 4);
        sm[row * QSTR + wpos(2 * c4)]     = pack2(v.x, v.y);
        sm[row * QSTR + wpos(2 * c4 + 1)] = pack2(v.z, v.w);
    }
    __syncthreads();
    uint32_t qa[4][4];
    #pragma unroll
    for (int kt = 0; kt < 4; kt++) {
        const uint32_t* p = &sm[(m0 + gid) * QSTR + kt * 8 + 2 * tig];
        uint2 lo = *(const uint2*)p;
        uint2 hi = *(const uint2*)(p + 8 * QSTR);
        qa[kt][0] = lo.x; qa[kt][1] = hi.x;
        qa[kt][2] = lo.y; qa[kt][3] = hi.y;
    }
    __syncthreads();   // staging done; buffers free

    float oacc[8][4];
    #pragma unroll
    for (int b = 0; b < 8; b++)
        #pragma unroll
        for (int c = 0; c < 4; c++) oacc[b][c] = 0.f;

    // prologue: start tile 0
    issue_tile(bh, 0, sbase, tid);
    CP_COMMIT();

    #pragma unroll 1
    for (int it = 0; it < NITER; it++) {
        if (it + 1 < NITER) {
            issue_tile(bh, it + 1, sbase + ((it + 1) & 1) * (BUFW * 4), tid);
            CP_COMMIT();
            CP_WAIT(1);            // tile it has landed
        } else {
            CP_WAIT(0);
        }
        __syncthreads();           // make all threads' copies visible

        const uint32_t* sK = sm + (it & 1) * BUFW;
        const uint32_t* sV = sK + KWORDS;

        #pragma unroll 2
        for (int nk = 0; nk < NK16; nk++) {
            float s0[4], s1[4];
            {   // S cols 16nk+0..7
                const uint32_t* kb = &sK[((2 * nk) * 8 + gid) * KSTR + 2 * tig];
                uint2 b0 = *(const uint2*)(kb);
                uint2 b1 = *(const uint2*)(kb + 8);
                uint2 b2 = *(const uint2*)(kb + 16);
                uint2 b3 = *(const uint2*)(kb + 24);
                float ta[4] = {0.f, 0.f, 0.f, 0.f};
                float tb[4] = {0.f, 0.f, 0.f, 0.f};
                mma16(ta, qa[0], b0.x, b0.y);
                mma16(tb, qa[1], b1.x, b1.y);
                mma16(ta, qa[2], b2.x, b2.y);
                mma16(tb, qa[3], b3.x, b3.y);
                s0[0] = ta[0] + tb[0]; s0[1] = ta[1] + tb[1];
                s0[2] = ta[2] + tb[2]; s0[3] = ta[3] + tb[3];
            }
            {   // S cols 16nk+8..15
                const uint32_t* kb = &sK[((2 * nk + 1) * 8 + gid) * KSTR + 2 * tig];
                uint2 b0 = *(const uint2*)(kb);
                uint2 b1 = *(const uint2*)(kb + 8);
                uint2 b2 = *(const uint2*)(kb + 16);
                uint2 b3 = *(const uint2*)(kb + 24);
                float ta[4] = {0.f, 0.f, 0.f, 0.f};
                float tb[4] = {0.f, 0.f, 0.f, 0.f};
                mma16(ta, qa[0], b0.x, b0.y);
                mma16(tb, qa[1], b1.x, b1.y);
                mma16(ta, qa[2], b2.x, b2.y);
                mma16(tb, qa[3], b3.x, b3.y);
                s1[0] = ta[0] + tb[0]; s1[1] = ta[1] + tb[1];
                s1[2] = ta[2] + tb[2]; s1[3] = ta[3] + tb[3];
            }
            // relu + pack: GEMM1 C-fragment == GEMM2 A-fragment
            uint32_t pa[4];
            pa[0] = pack2(fmaxf(s0[0], 0.f), fmaxf(s0[1], 0.f));
            pa[1] = pack2(fmaxf(s0[2], 0.f), fmaxf(s0[3], 0.f));
            pa[2] = pack2(fmaxf(s1[0], 0.f), fmaxf(s1[1], 0.f));
            pa[3] = pack2(fmaxf(s1[2], 0.f), fmaxf(s1[3], 0.f));

            const uint32_t* vb = &sV[(8 * nk + tig) * VSTR + gid];
            #pragma unroll
            for (int n2 = 0; n2 < 8; n2++) {
                uint32_t b0 = vb[n2 * 8];
                uint32_t b1 = vb[4 * VSTR + n2 * 8];
                mma16(oacc[n2], pa, b0, b1);
            }
        }
        __syncthreads();           // done reading buf it&1 before it's rewritten
    }

    // ---- Epilogue: O_out = O / 64 ----
    {
        float* r0 = Op + (size_t)(m0 + gid) * HD;
        float* r1 = r0 + 8 * HD;
        #pragma unroll
        for (int n2 = 0; n2 < 8; n2++) {
            int col = n2 * 8 + 2 * tig;
            *(float2*)(r0 + col) = make_float2(oacc[n2][0] * 0.015625f,
                                               oacc[n2][1] * 0.015625f);
            *(float2*)(r1 + col) = make_float2(oacc[n2][2] * 0.015625f,
                                               oacc[n2][3] * 0.015625f);
        }
    }
}

extern "C" void kernel_launch(void* const* d_in, const int* in_sizes, int n_in,
                              void* d_out, int out_size) {
    const float* q = (const float*)d_in[0];
    const float* k = (const float*)d_in[1];
    const float* v = (const float*)d_in[2];
    float* o = (float*)d_out;

    convert_kv<<<512, 512>>>(k, v);

    cudaFuncSetAttribute(dot_relu_attn_v8,
                         cudaFuncAttributeMaxDynamicSharedMemorySize, SMEM_BYTES);
    dim3 grid(SEQ / BM, BH);
    dot_relu_attn_v8<<<grid, NTH, SMEM_BYTES>>>(q, o);
}